// round 13
// baseline (speedup 1.0000x reference)
#include <cuda_runtime.h>
#include <cstdint>

#define N_NODES 100000
#define N_EDGES 3200000
#define N_FEAT  24
#define FPAD    32                 // padded feature stride (128 bytes)
#define LAYERS  6
#define EDGE_CAP 4000000           // padded total <= E + 7N = 3.9M
#define BUILD_BLOCKS  148
#define BUILD_THREADS 1024
#define CHUNK 676                  // ceil(N_NODES / BUILD_BLOCKS)

// ---------------------------------------------------------------------------
// Scratch (allocation-free rule: __device__ globals).
// Padded CSR: each row's g_edge segment is padded to a multiple of 8. Pad
// slots are NEVER written; __device__ globals are zero-init, so pads are
// permanently (val=0, off=0) -> harmless gathers of row 0 scaled by 0.
// Deterministic layout -> replay-safe. Feature buffers padded to FPAD=32
// floats (128B) so rows are line-aligned, but ONLY bytes 0..95 are ever
// requested (sector 3 is dead zero padding; see SpMM comment).
// ---------------------------------------------------------------------------
__device__ __align__(16) float  g_bufP[(size_t)N_NODES * FPAD];
__device__ __align__(16) float  g_bufQ[(size_t)N_NODES * FPAD];
__device__ __align__(16) float2 g_edge[EDGE_CAP];   // (val, col*128 bits)
__device__ int g_cnt[N_NODES];        // real row lengths (build only)
__device__ int g_rowptr[N_NODES + 1]; // PADDED exclusive prefix
__device__ int g_cursor[N_NODES];
__device__ int g_bsum[BUILD_BLOCKS];
__device__ int g_boff[BUILD_BLOCKS];
// Monotone: int32 inputs -> set to 1 every run (idempotent); int64 -> stays 0.
__device__ int g_flag = 0;
// Monotone ticket barrier counter; never reset -> replay-safe.
__device__ unsigned g_bar = 0;

// ---------------------------------------------------------------------------
// Software grid barrier (persistent build kernel; 148 blocks = wave 1).
// ---------------------------------------------------------------------------
__device__ __forceinline__ void grid_barrier() {
    __syncthreads();
    if (threadIdx.x == 0) {
        __threadfence();
        unsigned ticket = atomicAdd(&g_bar, 1u);
        unsigned target = (ticket / BUILD_BLOCKS + 1u) * BUILD_BLOCKS;
        unsigned v;
        do {
            asm volatile("ld.global.acquire.gpu.u32 %0, [%1];"
                         : "=r"(v) : "l"(&g_bar));
            if (v < target) __nanosleep(64);
        } while (v < target);
    }
    __syncthreads();
}

__device__ __forceinline__ int load_idx(const void* p, int e, int flag) {
    int v = (flag == 1) ? ((const int*)p)[e] : (int)((const long long*)p)[e];
    return min(max(v, 0), N_NODES - 1);   // fault guard
}

// ---------------------------------------------------------------------------
// Persistent single-launch CSR build + x copy-in:
//   phase 0: zero counts, dtype probe (JAX x64-off downcasts int64->int32;
//            odd int32 words all-zero iff buffer is int64), copy x -> bufP
//   phase 1: row histogram
//   phase 2: exclusive scan of counts padded to multiples of 8
//   phase 3: scatter (val, col*128) into row-sorted padded g_edge
// ---------------------------------------------------------------------------
__global__ void __launch_bounds__(BUILD_THREADS)
build_csr_kernel(const void* __restrict__ rptr,
                 const void* __restrict__ cptr,
                 const float* __restrict__ vals,
                 const float* __restrict__ x) {
    const int tid    = threadIdx.x;
    const int gid    = blockIdx.x * BUILD_THREADS + tid;
    const int stride = BUILD_BLOCKS * BUILD_THREADS;

    // --- phase 0 ---
    for (int i = gid; i < N_NODES; i += stride) g_cnt[i] = 0;
    const int* p32 = (const int*)rptr;
    for (int i = gid; i < N_EDGES / 2; i += stride)
        if (p32[2 * i + 1] != 0) g_flag = 1;
    for (int i = gid; i < N_NODES * N_FEAT; i += stride) {
        int r = i / N_FEAT, f = i - r * N_FEAT;
        g_bufP[r * FPAD + f] = x[i];
    }
    grid_barrier();

    const int flag = g_flag;

    // --- phase 1: histogram ---
    for (int e = gid; e < N_EDGES; e += stride)
        atomicAdd(&g_cnt[load_idx(rptr, e, flag)], 1);
    grid_barrier();

    // --- phase 2a: block-local exclusive scan of padded counts ---
    {
        __shared__ int s_w[32];
        int lane = tid & 31, wid = tid >> 5;
        int i = blockIdx.x * CHUNK + tid;
        int v = (tid < CHUNK && i < N_NODES) ? ((g_cnt[i] + 7) & ~7) : 0;
        int s = v;
        #pragma unroll
        for (int off = 1; off < 32; off <<= 1) {
            int n = __shfl_up_sync(0xffffffffu, s, off);
            if (lane >= off) s += n;
        }
        if (lane == 31) s_w[wid] = s;
        __syncthreads();
        if (wid == 0) {
            int ws = s_w[lane];
            #pragma unroll
            for (int off = 1; off < 32; off <<= 1) {
                int n = __shfl_up_sync(0xffffffffu, ws, off);
                if (lane >= off) ws += n;
            }
            s_w[lane] = ws;
        }
        __syncthreads();
        int woff = (wid > 0) ? s_w[wid - 1] : 0;
        if (tid < CHUNK && i < N_NODES) g_rowptr[i] = woff + s - v;
        if (tid == BUILD_THREADS - 1) g_bsum[blockIdx.x] = s_w[31];
    }
    grid_barrier();

    // --- phase 2b: block 0 scans the 148 block sums ---
    {
        __shared__ int sb[BUILD_BLOCKS];
        if (blockIdx.x == 0) {
            if (tid < BUILD_BLOCKS) sb[tid] = g_bsum[tid];
            __syncthreads();
            for (int off = 1; off < BUILD_BLOCKS; off <<= 1) {
                int t = (tid < BUILD_BLOCKS && tid >= off) ? sb[tid - off] : 0;
                __syncthreads();
                if (tid < BUILD_BLOCKS) sb[tid] += t;
                __syncthreads();
            }
            if (tid < BUILD_BLOCKS) g_boff[tid] = sb[tid] - g_bsum[tid];
            if (tid == BUILD_BLOCKS - 1) g_rowptr[N_NODES] = sb[BUILD_BLOCKS - 1];
        }
    }
    grid_barrier();

    // --- phase 2c: add block offsets; init cursors ---
    for (int i = gid; i < N_NODES; i += stride) {
        int r = g_rowptr[i] + g_boff[i / CHUNK];
        g_rowptr[i] = r;
        g_cursor[i] = r;
    }
    grid_barrier();

    // --- phase 3: place edges (payload: val, col*128 byte offset) ---
    for (int e = gid; e < N_EDGES; e += stride) {
        int r = load_idx(rptr, e, flag);
        int c = load_idx(cptr, e, flag);
        int pos = atomicAdd(&g_cursor[r], 1);
        g_edge[pos] = make_float2(vals[e], __int_as_float(c * (FPAD * 4)));
    }
}

// ---------------------------------------------------------------------------
// CSR SpMM, per-group edge loads, 96B gathers. One warp per row; lanes in
// 4 groups of 8 (g = lane>>3, q = lane&7). Per iteration (8 edges, 2 halves):
//   1x LDG.64 per half: group g loads edge (e+g) -- 4 addresses, 32 aligned
//     bytes, one wavefront, zero selects.
//   1x LDG.128 gather per half: lane offset min(q,5)*16 restricts requests
//     to bytes 0..95 of the row -- sector 3 (zero padding) is NEVER fetched,
//     cutting the dominant L2 stream by 25% (L2-BW-bound per R12 profile).
//     Lanes q=6,7 re-read sector 2 (no new sectors); their accumulators are
//     garbage but structurally discarded: the fold partners of each writing
//     lane (q, q+8, q+16, q+24) all share the same q < 6.
//   4x FFMA per half into the per-lane float4 accumulator.
// Rows padded to multiples of 8 with permanent-zero entries -> no masking.
// Epilogue: butterfly (xor 8, xor 16) folds the 4 groups; lanes 0-5 write
// one float4 each (24 floats; 96B rows stay 16B-aligned at stride 24).
// __launch_bounds__(256, 8) pins regs <= 32 -> 8 blocks/SM.
// ---------------------------------------------------------------------------
template <int DSTRIDE>
__global__ void __launch_bounds__(256, 8)
spmm_csr_kernel(const float* __restrict__ src, float* __restrict__ dst) {
    int w    = (blockIdx.x * blockDim.x + threadIdx.x) >> 5;  // row
    int lane = threadIdx.x & 31;

    int start = g_rowptr[w];          // multiple of 8
    int end   = g_rowptr[w + 1];      // padded end (pads contribute zero)

    int g = lane >> 3;                // edge-stream group 0..3
    int q = lane & 7;
    const char* sp = (const char*)src + min(q, 5) * 16;  // bytes 0..95 only

    float4 acc = make_float4(0.f, 0.f, 0.f, 0.f);

    for (int e = start; e < end; e += 8) {
        float2 e0 = g_edge[e + g];
        float2 e1 = g_edge[e + 4 + g];
        float4 g0 = *(const float4*)(sp + __float_as_int(e0.y));
        float4 g1 = *(const float4*)(sp + __float_as_int(e1.y));
        acc.x = fmaf(e0.x, g0.x, acc.x);
        acc.y = fmaf(e0.x, g0.y, acc.y);
        acc.z = fmaf(e0.x, g0.z, acc.z);
        acc.w = fmaf(e0.x, g0.w, acc.w);
        acc.x = fmaf(e1.x, g1.x, acc.x);
        acc.y = fmaf(e1.x, g1.y, acc.y);
        acc.z = fmaf(e1.x, g1.z, acc.z);
        acc.w = fmaf(e1.x, g1.w, acc.w);
    }

    // Fold the 4 edge-stream groups: lanes {q, q+8, q+16, q+24} -> lane q.
    acc.x += __shfl_xor_sync(0xffffffffu, acc.x, 8);
    acc.y += __shfl_xor_sync(0xffffffffu, acc.y, 8);
    acc.z += __shfl_xor_sync(0xffffffffu, acc.z, 8);
    acc.w += __shfl_xor_sync(0xffffffffu, acc.w, 8);
    acc.x += __shfl_xor_sync(0xffffffffu, acc.x, 16);
    acc.y += __shfl_xor_sync(0xffffffffu, acc.y, 16);
    acc.z += __shfl_xor_sync(0xffffffffu, acc.z, 16);
    acc.w += __shfl_xor_sync(0xffffffffu, acc.w, 16);

    if (lane < 6)   // lanes 0-5 cover feats 0..23 (float4 each)
        *(float4*)(dst + (size_t)w * DSTRIDE + lane * 4) = acc;
}

// ---------------------------------------------------------------------------
// kernel_launch: one build launch, then 6 SpMMs. x copied into padded bufP
// inside build; chain P->Q->P->Q->P->Q->out (final instantiation writes at
// stride 24). Default stream, no syncs, no allocations -> graph-capturable.
// ---------------------------------------------------------------------------
extern "C" void kernel_launch(void* const* d_in, const int* in_sizes, int n_in,
                              void* d_out, int out_size) {
    const float* x    = (const float*)d_in[0];  // [N_NODES, N_FEAT]
    const float* vals = (const float*)d_in[1];  // [N_EDGES]
    const void*  rraw = d_in[2];                // [N_EDGES] int32 or int64
    const void*  craw = d_in[3];                // [N_EDGES] int32 or int64
    float* out = (float*)d_out;                 // [N_NODES, N_FEAT]

    float* bufP;
    float* bufQ;
    cudaGetSymbolAddress((void**)&bufP, g_bufP);
    cudaGetSymbolAddress((void**)&bufQ, g_bufQ);

    const int sblocks = N_NODES / 8;   // 12500 blocks, warp per row

    build_csr_kernel<<<BUILD_BLOCKS, BUILD_THREADS>>>(rraw, craw, vals, x);

    // Layers 1-5 into padded buffers, final layer into d_out (stride 24).
    spmm_csr_kernel<FPAD><<<sblocks, 256>>>(bufP, bufQ);
    spmm_csr_kernel<FPAD><<<sblocks, 256>>>(bufQ, bufP);
    spmm_csr_kernel<FPAD><<<sblocks, 256>>>(bufP, bufQ);
    spmm_csr_kernel<FPAD><<<sblocks, 256>>>(bufQ, bufP);
    spmm_csr_kernel<FPAD><<<sblocks, 256>>>(bufP, bufQ);
    spmm_csr_kernel<N_FEAT><<<sblocks, 256>>>(bufQ, out);
}

// round 14
// speedup vs baseline: 1.0404x; 1.0404x over previous
#include <cuda_runtime.h>
#include <cstdint>

#define N_NODES 100000
#define N_EDGES 3200000
#define N_FEAT  24
#define FPAD    32                 // padded feature stride (128 bytes)
#define LAYERS  6
#define EDGE_CAP 4000000           // padded total <= E + 7N = 3.9M
#define BUILD_BLOCKS  148
#define BUILD_THREADS 1024
#define CHUNK 676                  // ceil(N_NODES / BUILD_BLOCKS)

// ---------------------------------------------------------------------------
// Scratch (allocation-free rule: __device__ globals).
// Padded CSR: each row's g_edge segment is padded to a multiple of 8. Pad
// slots are NEVER written; __device__ globals are zero-init, so pads are
// permanently (val=0, off=0) -> harmless gathers of row 0 scaled by 0.
// Deterministic layout -> replay-safe. Feature buffers padded to FPAD=32
// floats (128B) so rows are line-aligned; only bytes 0..95 are requested.
// ---------------------------------------------------------------------------
__device__ __align__(16) float  g_bufP[(size_t)N_NODES * FPAD];
__device__ __align__(16) float  g_bufQ[(size_t)N_NODES * FPAD];
__device__ __align__(16) float2 g_edge[EDGE_CAP];   // (val, col*128 bits)
__device__ int g_cnt[N_NODES];        // real row lengths (build only)
__device__ int g_rowptr[N_NODES + 1]; // PADDED exclusive prefix
__device__ int g_cursor[N_NODES];
__device__ int g_bsum[BUILD_BLOCKS];
__device__ int g_boff[BUILD_BLOCKS];
// Monotone: int32 inputs -> set to 1 every run (idempotent); int64 -> stays 0.
__device__ int g_flag = 0;
// Monotone ticket barrier counter; never reset -> replay-safe.
__device__ unsigned g_bar = 0;

// ---------------------------------------------------------------------------
// Software grid barrier (persistent build kernel; 148 blocks = wave 1).
// ---------------------------------------------------------------------------
__device__ __forceinline__ void grid_barrier() {
    __syncthreads();
    if (threadIdx.x == 0) {
        __threadfence();
        unsigned ticket = atomicAdd(&g_bar, 1u);
        unsigned target = (ticket / BUILD_BLOCKS + 1u) * BUILD_BLOCKS;
        unsigned v;
        do {
            asm volatile("ld.global.acquire.gpu.u32 %0, [%1];"
                         : "=r"(v) : "l"(&g_bar));
            if (v < target) __nanosleep(64);
        } while (v < target);
    }
    __syncthreads();
}

__device__ __forceinline__ int load_idx(const void* p, int e, int flag) {
    int v = (flag == 1) ? ((const int*)p)[e] : (int)((const long long*)p)[e];
    return min(max(v, 0), N_NODES - 1);   // fault guard
}

// ---------------------------------------------------------------------------
// Persistent single-launch CSR build + x copy-in:
//   phase 0: zero counts, dtype probe (JAX x64-off downcasts int64->int32;
//            odd int32 words all-zero iff buffer is int64), copy x -> bufP
//   phase 1: row histogram
//   phase 2: exclusive scan of counts padded to multiples of 8
//   phase 3: scatter (val, col*128) into row-sorted padded g_edge
// ---------------------------------------------------------------------------
__global__ void __launch_bounds__(BUILD_THREADS)
build_csr_kernel(const void* __restrict__ rptr,
                 const void* __restrict__ cptr,
                 const float* __restrict__ vals,
                 const float* __restrict__ x) {
    const int tid    = threadIdx.x;
    const int gid    = blockIdx.x * BUILD_THREADS + tid;
    const int stride = BUILD_BLOCKS * BUILD_THREADS;

    // --- phase 0 ---
    for (int i = gid; i < N_NODES; i += stride) g_cnt[i] = 0;
    const int* p32 = (const int*)rptr;
    for (int i = gid; i < N_EDGES / 2; i += stride)
        if (p32[2 * i + 1] != 0) g_flag = 1;
    for (int i = gid; i < N_NODES * N_FEAT; i += stride) {
        int r = i / N_FEAT, f = i - r * N_FEAT;
        g_bufP[r * FPAD + f] = x[i];
    }
    grid_barrier();

    const int flag = g_flag;

    // --- phase 1: histogram ---
    for (int e = gid; e < N_EDGES; e += stride)
        atomicAdd(&g_cnt[load_idx(rptr, e, flag)], 1);
    grid_barrier();

    // --- phase 2a: block-local exclusive scan of padded counts ---
    {
        __shared__ int s_w[32];
        int lane = tid & 31, wid = tid >> 5;
        int i = blockIdx.x * CHUNK + tid;
        int v = (tid < CHUNK && i < N_NODES) ? ((g_cnt[i] + 7) & ~7) : 0;
        int s = v;
        #pragma unroll
        for (int off = 1; off < 32; off <<= 1) {
            int n = __shfl_up_sync(0xffffffffu, s, off);
            if (lane >= off) s += n;
        }
        if (lane == 31) s_w[wid] = s;
        __syncthreads();
        if (wid == 0) {
            int ws = s_w[lane];
            #pragma unroll
            for (int off = 1; off < 32; off <<= 1) {
                int n = __shfl_up_sync(0xffffffffu, ws, off);
                if (lane >= off) ws += n;
            }
            s_w[lane] = ws;
        }
        __syncthreads();
        int woff = (wid > 0) ? s_w[wid - 1] : 0;
        if (tid < CHUNK && i < N_NODES) g_rowptr[i] = woff + s - v;
        if (tid == BUILD_THREADS - 1) g_bsum[blockIdx.x] = s_w[31];
    }
    grid_barrier();

    // --- phase 2b: block 0 scans the 148 block sums ---
    {
        __shared__ int sb[BUILD_BLOCKS];
        if (blockIdx.x == 0) {
            if (tid < BUILD_BLOCKS) sb[tid] = g_bsum[tid];
            __syncthreads();
            for (int off = 1; off < BUILD_BLOCKS; off <<= 1) {
                int t = (tid < BUILD_BLOCKS && tid >= off) ? sb[tid - off] : 0;
                __syncthreads();
                if (tid < BUILD_BLOCKS) sb[tid] += t;
                __syncthreads();
            }
            if (tid < BUILD_BLOCKS) g_boff[tid] = sb[tid] - g_bsum[tid];
            if (tid == BUILD_BLOCKS - 1) g_rowptr[N_NODES] = sb[BUILD_BLOCKS - 1];
        }
    }
    grid_barrier();

    // --- phase 2c: add block offsets; init cursors ---
    for (int i = gid; i < N_NODES; i += stride) {
        int r = g_rowptr[i] + g_boff[i / CHUNK];
        g_rowptr[i] = r;
        g_cursor[i] = r;
    }
    grid_barrier();

    // --- phase 3: place edges (payload: val, col*128 byte offset) ---
    for (int e = gid; e < N_EDGES; e += stride) {
        int r = load_idx(rptr, e, flag);
        int c = load_idx(cptr, e, flag);
        int pos = atomicAdd(&g_cursor[r], 1);
        g_edge[pos] = make_float2(vals[e], __int_as_float(c * (FPAD * 4)));
    }
}

// ---------------------------------------------------------------------------
// CSR SpMM, per-group edge loads + SOFTWARE-PIPELINED edge prefetch.
// One warp per row; lanes in 4 groups of 8 (g = lane>>3, q = lane&7).
// The R13 plateau showed nothing saturated (L1 63 / issue 40 / L2 36):
// latency-bound on the per-iteration edge-load -> dependent-gather chain.
// Fix: issue batch i+1's edge loads BEFORE batch i's gathers, so the edge
// latency overlaps the gather latency (chain: max instead of sum).
// Per iteration (8 edges): 2x prefetch LDG.64 (next batch) + 2x LDG.128
// gather (96B of the row: lane offset min(q,5)*16 skips the dead pad
// sector; lanes q=6,7 re-read sector 2 and are structurally discarded by
// the fold) + 8 FFMA. Prefetch overreads at the row boundary hit the next
// row's / pad entries and are never consumed -- always within EDGE_CAP.
// Rows padded to multiples of 8 with permanent-zero entries -> no masking.
// Epilogue: butterfly (xor 8, xor 16) folds the 4 groups; lanes 0-5 write
// one float4 each. __launch_bounds__(256, 8) pins regs <= 32 -> 8 blocks/SM.
// ---------------------------------------------------------------------------
template <int DSTRIDE>
__global__ void __launch_bounds__(256, 8)
spmm_csr_kernel(const float* __restrict__ src, float* __restrict__ dst) {
    int w    = (blockIdx.x * blockDim.x + threadIdx.x) >> 5;  // row
    int lane = threadIdx.x & 31;

    int start = g_rowptr[w];          // multiple of 8
    int end   = g_rowptr[w + 1];      // padded end (pads contribute zero)

    int g = lane >> 3;                // edge-stream group 0..3
    int q = lane & 7;

    if (start == end) {               // empty row (astronomically rare)
        if (lane < 6)
            *(float4*)(dst + (size_t)w * DSTRIDE + lane * 4) =
                make_float4(0.f, 0.f, 0.f, 0.f);
        return;
    }

    const char* sp = (const char*)src + min(q, 5) * 16;  // bytes 0..95 only

    float4 acc = make_float4(0.f, 0.f, 0.f, 0.f);

    // Prologue: batch 0's edges.
    float2 e0 = g_edge[start + g];
    float2 e1 = g_edge[start + 4 + g];

    int e = start;
    for (; e + 8 < end; e += 8) {
        // Prefetch batch i+1's edges FIRST (independent of current gathers).
        float2 n0 = g_edge[e + 8 + g];
        float2 n1 = g_edge[e + 12 + g];
        float4 g0 = *(const float4*)(sp + __float_as_int(e0.y));
        float4 g1 = *(const float4*)(sp + __float_as_int(e1.y));
        acc.x = fmaf(e0.x, g0.x, acc.x);
        acc.y = fmaf(e0.x, g0.y, acc.y);
        acc.z = fmaf(e0.x, g0.z, acc.z);
        acc.w = fmaf(e0.x, g0.w, acc.w);
        acc.x = fmaf(e1.x, g1.x, acc.x);
        acc.y = fmaf(e1.x, g1.y, acc.y);
        acc.z = fmaf(e1.x, g1.z, acc.z);
        acc.w = fmaf(e1.x, g1.w, acc.w);
        e0 = n0;
        e1 = n1;
    }
    // Epilogue batch (no prefetch).
    {
        float4 g0 = *(const float4*)(sp + __float_as_int(e0.y));
        float4 g1 = *(const float4*)(sp + __float_as_int(e1.y));
        acc.x = fmaf(e0.x, g0.x, acc.x);
        acc.y = fmaf(e0.x, g0.y, acc.y);
        acc.z = fmaf(e0.x, g0.z, acc.z);
        acc.w = fmaf(e0.x, g0.w, acc.w);
        acc.x = fmaf(e1.x, g1.x, acc.x);
        acc.y = fmaf(e1.x, g1.y, acc.y);
        acc.z = fmaf(e1.x, g1.z, acc.z);
        acc.w = fmaf(e1.x, g1.w, acc.w);
    }

    // Fold the 4 edge-stream groups: lanes {q, q+8, q+16, q+24} -> lane q.
    acc.x += __shfl_xor_sync(0xffffffffu, acc.x, 8);
    acc.y += __shfl_xor_sync(0xffffffffu, acc.y, 8);
    acc.z += __shfl_xor_sync(0xffffffffu, acc.z, 8);
    acc.w += __shfl_xor_sync(0xffffffffu, acc.w, 8);
    acc.x += __shfl_xor_sync(0xffffffffu, acc.x, 16);
    acc.y += __shfl_xor_sync(0xffffffffu, acc.y, 16);
    acc.z += __shfl_xor_sync(0xffffffffu, acc.z, 16);
    acc.w += __shfl_xor_sync(0xffffffffu, acc.w, 16);

    if (lane < 6)   // lanes 0-5 cover feats 0..23 (float4 each)
        *(float4*)(dst + (size_t)w * DSTRIDE + lane * 4) = acc;
}

// ---------------------------------------------------------------------------
// kernel_launch: one build launch, then 6 SpMMs. x copied into padded bufP
// inside build; chain P->Q->P->Q->P->Q->out (final instantiation writes at
// stride 24). Default stream, no syncs, no allocations -> graph-capturable.
// ---------------------------------------------------------------------------
extern "C" void kernel_launch(void* const* d_in, const int* in_sizes, int n_in,
                              void* d_out, int out_size) {
    const float* x    = (const float*)d_in[0];  // [N_NODES, N_FEAT]
    const float* vals = (const float*)d_in[1];  // [N_EDGES]
    const void*  rraw = d_in[2];                // [N_EDGES] int32 or int64
    const void*  craw = d_in[3];                // [N_EDGES] int32 or int64
    float* out = (float*)d_out;                 // [N_NODES, N_FEAT]

    float* bufP;
    float* bufQ;
    cudaGetSymbolAddress((void**)&bufP, g_bufP);
    cudaGetSymbolAddress((void**)&bufQ, g_bufQ);

    const int sblocks = N_NODES / 8;   // 12500 blocks, warp per row

    build_csr_kernel<<<BUILD_BLOCKS, BUILD_THREADS>>>(rraw, craw, vals, x);

    // Layers 1-5 into padded buffers, final layer into d_out (stride 24).
    spmm_csr_kernel<FPAD><<<sblocks, 256>>>(bufP, bufQ);
    spmm_csr_kernel<FPAD><<<sblocks, 256>>>(bufQ, bufP);
    spmm_csr_kernel<FPAD><<<sblocks, 256>>>(bufP, bufQ);
    spmm_csr_kernel<FPAD><<<sblocks, 256>>>(bufQ, bufP);
    spmm_csr_kernel<FPAD><<<sblocks, 256>>>(bufP, bufQ);
    spmm_csr_kernel<N_FEAT><<<sblocks, 256>>>(bufQ, out);
}